// round 14
// baseline (speedup 1.0000x reference)
#include <cuda_runtime.h>
#include <cuda_fp16.h>
#include <cstdint>

// ============================================================================
// OutlierAwareLinear: y = x @ W^T + b, then per-token outlier-aware fake quant.
// GEMM: 3-term FP16 split (hi/lo) on mma.sync.m16n8k16.f16.f32.
//   a*b ~= ah*bh + ah*bl + al*bh   (al*bl ~2^-22 dropped; fp32-like accuracy)
// x,W pre-split once into fp16 hi/lo; GEMM streams them via cp.async.
// THIS ROUND: B fragments double-buffered in registers — the 2 B-ldsm for
// ntp+1 are issued BEFORE the 12 HMMAs of ntp, moving the ldsm->mma
// dependency distance from ~1 issue to ~12 (96 cyc > 29-cyc LDS latency).
// This targets the ~1490 cyc/chunk of tensor idle that survived every fill-
// strategy change (R8/R9/R12 all ~78-80% tensor).
// ============================================================================

#define M_DIM 16384
#define K_DIM 2048
#define N_DIM 2048
#define BM 128
#define BN 256
#define BK 64                    // 64 fp16 = 128 bytes per row
#define NCHUNKS (K_DIM / BK)     // 32

// smem per buffer: Ahi 16K | Alo 16K | Bhi 32K | Blo 32K = 96KB; 2 buffers
#define OFF_AHI 0
#define OFF_ALO 16384
#define OFF_BHI 32768
#define OFF_BLO 65536
#define BUF_STRIDE 98304
#define SMEM_TOTAL (2 * BUF_STRIDE)   // 192 KB

// ---- global fp16 hi/lo scratch (static __device__; no runtime alloc) ----
__device__ __half g_Ahi[(size_t)M_DIM * K_DIM];   // 64 MB
__device__ __half g_Alo[(size_t)M_DIM * K_DIM];   // 64 MB
__device__ __half g_Whi[(size_t)N_DIM * K_DIM];   // 8 MB
__device__ __half g_Wlo[(size_t)N_DIM * K_DIM];   // 8 MB

__device__ __forceinline__ uint32_t smem_u32(const void* p) {
    return (uint32_t)__cvta_generic_to_shared(p);
}
__device__ __forceinline__ uint32_t swz(uint32_t off) {
    return off ^ ((off >> 3) & 0x70);
}
__device__ __forceinline__ void ldsm_x4(uint32_t r[4], uint32_t addr) {
    asm volatile("ldmatrix.sync.aligned.m8n8.x4.shared.b16 {%0,%1,%2,%3}, [%4];"
                 : "=r"(r[0]), "=r"(r[1]), "=r"(r[2]), "=r"(r[3]) : "r"(addr));
}
__device__ __forceinline__ void mma_f16(float c[4], const uint32_t a[4],
                                        const uint32_t* b) {
    asm volatile(
        "mma.sync.aligned.m16n8k16.row.col.f32.f16.f16.f32 "
        "{%0,%1,%2,%3}, {%4,%5,%6,%7}, {%8,%9}, {%0,%1,%2,%3};"
        : "+f"(c[0]), "+f"(c[1]), "+f"(c[2]), "+f"(c[3])
        : "r"(a[0]), "r"(a[1]), "r"(a[2]), "r"(a[3]), "r"(b[0]), "r"(b[1]));
}
__device__ __forceinline__ void cp16(uint32_t dst, const void* src) {
    asm volatile("cp.async.cg.shared.global [%0], [%1], 16;" :: "r"(dst), "l"(src));
}
#define CP_COMMIT() asm volatile("cp.async.commit_group;" ::: "memory")
#define CP_WAIT1()  asm volatile("cp.async.wait_group 1;" ::: "memory")

// ---------------------------------------------------------------------------
// Split kernel: x and W -> fp16 (hi, lo). One float4 per thread.
// ---------------------------------------------------------------------------
#define NX4 ((size_t)M_DIM * K_DIM / 4)
#define NW4 ((size_t)N_DIM * K_DIM / 4)

__global__ __launch_bounds__(256)
void oal_split_kernel(const float4* __restrict__ x4, const float4* __restrict__ w4) {
    const size_t i = (size_t)blockIdx.x * blockDim.x + threadIdx.x;
    float4 v;
    __half2 *hi, *lo;
    size_t o;
    if (i < NX4) {
        v = x4[i];
        hi = (__half2*)g_Ahi; lo = (__half2*)g_Alo; o = i * 2;
    } else if (i < NX4 + NW4) {
        v = w4[i - NX4];
        hi = (__half2*)g_Whi; lo = (__half2*)g_Wlo; o = (i - NX4) * 2;
    } else return;

    __half2 h0 = __floats2half2_rn(v.x, v.y);
    __half2 h1 = __floats2half2_rn(v.z, v.w);
    float2 f0 = __half22float2(h0);
    float2 f1 = __half22float2(h1);
    hi[o]     = h0;
    hi[o + 1] = h1;
    lo[o]     = __floats2half2_rn(v.x - f0.x, v.y - f0.y);
    lo[o + 1] = __floats2half2_rn(v.z - f1.x, v.w - f1.y);
}

// ---------------------------------------------------------------------------
// GEMM: CTA 128x256, 8 warps (4M x 2N), warp tile 32x128, fp16 hi/lo 3-term.
// ---------------------------------------------------------------------------
__global__ __launch_bounds__(256, 1)
void oal_gemm_f16(const float* __restrict__ bias, float* __restrict__ Y) {
    extern __shared__ char smem[];
    const uint32_t sb = smem_u32(smem);

    const int tid = threadIdx.x;
    const int lane = tid & 31;
    const int wid = tid >> 5;
    const int warp_m = (wid & 3) * 32;
    const int warp_n = (wid >> 2) * 128;
    const int block_m = blockIdx.y * BM;
    const int block_n = blockIdx.x * BN;

    // ldmatrix lane offsets (unswizzled; swizzle via XOR at use — proven)
    const uint32_t swmask = (lane & 7) << 4;
    uint32_t a_off[2];
#pragma unroll
    for (int mt = 0; mt < 2; mt++) {
        uint32_t row = warp_m + mt * 16 + (lane & 15);
        a_off[mt] = row * 128 + (lane >> 4) * 16;
    }
    uint32_t b_off[8];
#pragma unroll
    for (int ntp = 0; ntp < 8; ntp++) {
        uint32_t n = warp_n + ntp * 16 + ((lane >> 4) & 1) * 8 + (lane & 7);
        b_off[ntp] = n * 128 + ((lane >> 3) & 1) * 16;
    }

    // producer mapping
    const int r8 = tid >> 3;
    const int c16 = (tid & 7) * 16;
    const int kseg8 = (tid & 7) * 8;

    const __half* Ahi = g_Ahi + (size_t)(block_m + r8) * K_DIM + kseg8;
    const __half* Alo = g_Alo + (size_t)(block_m + r8) * K_DIM + kseg8;
    const __half* Bhi = g_Whi + (size_t)(block_n + r8) * K_DIM + kseg8;
    const __half* Blo = g_Wlo + (size_t)(block_n + r8) * K_DIM + kseg8;

    float acc[2][16][4];
#pragma unroll
    for (int mt = 0; mt < 2; mt++)
#pragma unroll
        for (int nt = 0; nt < 16; nt++)
#pragma unroll
            for (int j = 0; j < 4; j++) acc[mt][nt][j] = 0.0f;

    // fill chunk c into buffer b (24 x cp.async 16B per thread)
    auto fill = [&](int c, int b) {
        const uint32_t base = sb + b * BUF_STRIDE;
        const int k0 = c * BK;
#pragma unroll
        for (int p = 0; p < 4; p++) {
            const uint32_t sw = swz((r8 + p * 32) * 128 + c16);
            cp16(base + OFF_AHI + sw, Ahi + (size_t)(p * 32) * K_DIM + k0);
            cp16(base + OFF_ALO + sw, Alo + (size_t)(p * 32) * K_DIM + k0);
        }
#pragma unroll
        for (int p = 0; p < 8; p++) {
            const uint32_t sw = swz((r8 + p * 32) * 128 + c16);
            cp16(base + OFF_BHI + sw, Bhi + (size_t)(p * 32) * K_DIM + k0);
            cp16(base + OFF_BLO + sw, Blo + (size_t)(p * 32) * K_DIM + k0);
        }
    };

    fill(0, 0); CP_COMMIT();
    fill(1, 1); CP_COMMIT();

    for (int c = 0; c < NCHUNKS; c++) {
        const int b = c & 1;
        const uint32_t cur = sb + b * BUF_STRIDE;

        CP_WAIT1();
        __syncthreads();

#pragma unroll
        for (int ks = 0; ks < 4; ks++) {
            uint32_t ah[2][4], al[2][4];
#pragma unroll
            for (int mt = 0; mt < 2; mt++) {
                const uint32_t ao = (a_off[mt] + ks * 32) ^ swmask;
                ldsm_x4(ah[mt], cur + OFF_AHI + ao);
                ldsm_x4(al[mt], cur + OFF_ALO + ao);
            }

            // B fragments double-buffered in registers: ldsm for ntp+1 is
            // issued BEFORE the HMMAs of ntp -> ldsm->mma distance ~12
            // issues (~96 cyc) instead of ~1, hiding the LDS latency.
            uint32_t bh[2][4], bl[2][4];
            {
                const uint32_t bo0 = (b_off[0] + ks * 32) ^ swmask;
                ldsm_x4(bh[0], cur + OFF_BHI + bo0);
                ldsm_x4(bl[0], cur + OFF_BLO + bo0);
            }
#pragma unroll
            for (int ntp = 0; ntp < 8; ntp++) {
                const int cb = ntp & 1;
                if (ntp < 7) {
                    const uint32_t bon = (b_off[ntp + 1] + ks * 32) ^ swmask;
                    ldsm_x4(bh[cb ^ 1], cur + OFF_BHI + bon);
                    ldsm_x4(bl[cb ^ 1], cur + OFF_BLO + bon);
                }
                // term-major issue; per-quad order hh, hl, lh (bit-identical)
#pragma unroll
                for (int t = 0; t < 2; t++)
#pragma unroll
                    for (int mt = 0; mt < 2; mt++)
                        mma_f16(acc[mt][2 * ntp + t], ah[mt], bh[cb] + 2 * t);  // hi*hi
#pragma unroll
                for (int t = 0; t < 2; t++)
#pragma unroll
                    for (int mt = 0; mt < 2; mt++)
                        mma_f16(acc[mt][2 * ntp + t], ah[mt], bl[cb] + 2 * t);  // hi*lo
#pragma unroll
                for (int t = 0; t < 2; t++)
#pragma unroll
                    for (int mt = 0; mt < 2; mt++)
                        mma_f16(acc[mt][2 * ntp + t], al[mt], bh[cb] + 2 * t);  // lo*hi
            }
        }

        __syncthreads();
        if (c + 2 < NCHUNKS) fill(c + 2, b);
        CP_COMMIT();
    }

    // ---- epilogue: acc -> gmem with bias ----
    const int g = lane >> 2;
    const int t4 = lane & 3;
#pragma unroll
    for (int mt = 0; mt < 2; mt++) {
        const int m0 = block_m + warp_m + mt * 16 + g;
#pragma unroll
        for (int nt = 0; nt < 16; nt++) {
            const int n0 = block_n + warp_n + nt * 8 + t4 * 2;
            const float2 bb = *(const float2*)(bias + n0);
            float2 v0, v1;
            v0.x = acc[mt][nt][0] + bb.x;
            v0.y = acc[mt][nt][1] + bb.y;
            v1.x = acc[mt][nt][2] + bb.x;
            v1.y = acc[mt][nt][3] + bb.y;
            *(float2*)(Y + (size_t)m0 * N_DIM + n0) = v0;
            *(float2*)(Y + (size_t)(m0 + 8) * N_DIM + n0) = v1;
        }
    }
}

// ---------------------------------------------------------------------------
// Per-token outlier-aware fake quant (66% of HBM peak).
// ---------------------------------------------------------------------------
#define QMAX 127.0f
#define OUTLIER_T 3.0f
#define Q_EPS 1e-6f

__global__ __launch_bounds__(256)
void oal_quant_kernel(float* __restrict__ Y) {
    const size_t row = blockIdx.x;
    float4* y4 = reinterpret_cast<float4*>(Y + row * (size_t)N_DIM);

    const int tid = threadIdx.x;
    float4 p = y4[tid];
    float4 q = y4[tid + 256];
    float v[8] = {p.x, p.y, p.z, p.w, q.x, q.y, q.z, q.w};

    float s = 0.0f, ss = 0.0f, amax = 0.0f;
#pragma unroll
    for (int i = 0; i < 8; i++) {
        s += v[i];
        ss = fmaf(v[i], v[i], ss);
        amax = fmaxf(amax, fabsf(v[i]));
    }
#pragma unroll
    for (int off = 16; off > 0; off >>= 1) {
        s += __shfl_xor_sync(0xFFFFFFFFu, s, off);
        ss += __shfl_xor_sync(0xFFFFFFFFu, ss, off);
        amax = fmaxf(amax, __shfl_xor_sync(0xFFFFFFFFu, amax, off));
    }

    __shared__ float red_s[8], red_ss[8], red_m[8];
    const int wid = tid >> 5;
    const int lid = tid & 31;
    if (lid == 0) { red_s[wid] = s; red_ss[wid] = ss; red_m[wid] = amax; }
    __syncthreads();

    if (wid == 0) {
        float s2 = (lid < 8) ? red_s[lid] : 0.0f;
        float ss2 = (lid < 8) ? red_ss[lid] : 0.0f;
        float m2 = (lid < 8) ? red_m[lid] : 0.0f;
#pragma unroll
        for (int off = 4; off > 0; off >>= 1) {
            s2 += __shfl_xor_sync(0xFFFFFFFFu, s2, off);
            ss2 += __shfl_xor_sync(0xFFFFFFFFu, ss2, off);
            m2 = fmaxf(m2, __shfl_xor_sync(0xFFFFFFFFu, m2, off));
        }
        if (lid == 0) { red_s[0] = s2; red_ss[0] = ss2; red_m[0] = m2; }
    }
    __syncthreads();

    const float inv_d = 1.0f / (float)N_DIM;
    const float mean = red_s[0] * inv_d;
    const float var = fmaxf(red_ss[0] * inv_d - mean * mean, 0.0f);
    const float thr = OUTLIER_T * sqrtf(var);
    const float scale = fmaxf(fminf(red_m[0], thr) / QMAX, Q_EPS);
    const float inv_scale = 1.0f / scale;

#pragma unroll
    for (int i = 0; i < 8; i++) {
        float x = v[i];
        float cl = fminf(fmaxf(x, -thr), thr);
        float fq = rintf(cl * inv_scale) * scale;
        v[i] = (fabsf(x) > thr) ? x : fq;
    }

    p.x = v[0]; p.y = v[1]; p.z = v[2]; p.w = v[3];
    q.x = v[4]; q.y = v[5]; q.z = v[6]; q.w = v[7];
    y4[tid] = p;
    y4[tid + 256] = q;
}

// Padding: captured ncu slot is our 4th launch; 2 nops put the GEMM there.
__global__ void oal_nop_kernel() {}

// ---------------------------------------------------------------------------

extern "C" void kernel_launch(void* const* d_in, const int* in_sizes, int n_in,
                              void* d_out, int out_size) {
    const float* x = (const float*)d_in[0];
    const float* W = (const float*)d_in[1];
    const float* b = (const float*)d_in[2];
    float* out = (float*)d_out;

    cudaFuncSetAttribute(oal_gemm_f16, cudaFuncAttributeMaxDynamicSharedMemorySize, SMEM_TOTAL);

    // 1) split x and W into fp16 hi/lo (~45us, bandwidth-bound)
    const size_t total4 = NX4 + NW4;
    const int sblocks = (int)((total4 + 255) / 256);
    oal_split_kernel<<<sblocks, 256>>>((const float4*)x, (const float4*)W);

    // 2-3) nops so the GEMM lands in the ncu capture slot (launch #4)
    oal_nop_kernel<<<1, 32>>>();
    oal_nop_kernel<<<1, 32>>>();

    // 4) GEMM
    dim3 ggrid(N_DIM / BN, M_DIM / BM);   // (8, 128)
    oal_gemm_f16<<<ggrid, 256, SMEM_TOTAL>>>(b, out);

    // 5) per-token quant
    oal_quant_kernel<<<M_DIM, 256>>>(out);
}

// round 15
// speedup vs baseline: 1.0241x; 1.0241x over previous
#include <cuda_runtime.h>
#include <cuda_fp16.h>
#include <cstdint>

// ============================================================================
// OutlierAwareLinear: y = x @ W^T + b, then per-token outlier-aware fake quant.
// GEMM: 3-term FP16 split (hi/lo) on mma.sync.m16n8k16.f16.f32:
//   a*b ~= ah*bh + ah*bl + al*bh  (al*bl ~2^-22 dropped; fp32-like accuracy)
// W pre-split once (16 MB) -> cp.async. A (x) split in-GEMM from fp32
// (register staging 3 chunks ahead) -- R9 structure, best bench total.
// MMA issue is term-major (R13): same accumulator quad touched every 4th
// HMMA instead of 3 consecutive (~30us faster GEMM at equal numerics).
// Profiling nops removed (~8us).
// ============================================================================

#define M_DIM 16384
#define K_DIM 2048
#define N_DIM 2048
#define BM 128
#define BN 256
#define BK 64                    // 64 fp16 = 128 bytes per row
#define NCHUNKS (K_DIM / BK)     // 32

// smem per buffer: Ahi 16K | Alo 16K | Bhi 32K | Blo 32K = 96KB; 2 buffers
#define OFF_AHI 0
#define OFF_ALO 16384
#define OFF_BHI 32768
#define OFF_BLO 65536
#define BUF_STRIDE 98304
#define SMEM_TOTAL (2 * BUF_STRIDE)   // 192 KB

// ---- global fp16 hi/lo scratch for W only (static; no runtime alloc) ----
__device__ __half g_Whi[(size_t)N_DIM * K_DIM];   // 8 MB
__device__ __half g_Wlo[(size_t)N_DIM * K_DIM];   // 8 MB

__device__ __forceinline__ uint32_t smem_u32(const void* p) {
    return (uint32_t)__cvta_generic_to_shared(p);
}
__device__ __forceinline__ uint32_t swz(uint32_t off) {
    return off ^ ((off >> 3) & 0x70);
}
__device__ __forceinline__ void ldsm_x4(uint32_t r[4], uint32_t addr) {
    asm volatile("ldmatrix.sync.aligned.m8n8.x4.shared.b16 {%0,%1,%2,%3}, [%4];"
                 : "=r"(r[0]), "=r"(r[1]), "=r"(r[2]), "=r"(r[3]) : "r"(addr));
}
__device__ __forceinline__ void mma_f16(float c[4], const uint32_t a[4],
                                        const uint32_t* b) {
    asm volatile(
        "mma.sync.aligned.m16n8k16.row.col.f32.f16.f16.f32 "
        "{%0,%1,%2,%3}, {%4,%5,%6,%7}, {%8,%9}, {%0,%1,%2,%3};"
        : "+f"(c[0]), "+f"(c[1]), "+f"(c[2]), "+f"(c[3])
        : "r"(a[0]), "r"(a[1]), "r"(a[2]), "r"(a[3]), "r"(b[0]), "r"(b[1]));
}
__device__ __forceinline__ void cp16(uint32_t dst, const void* src) {
    asm volatile("cp.async.cg.shared.global [%0], [%1], 16;" :: "r"(dst), "l"(src));
}
#define CP_COMMIT() asm volatile("cp.async.commit_group;" ::: "memory")
#define CP_WAIT1()  asm volatile("cp.async.wait_group 1;" ::: "memory")

// ---------------------------------------------------------------------------
// W split kernel: W -> fp16 (hi, lo). One float4 per thread. ~16 MB total.
// ---------------------------------------------------------------------------
#define NW4 ((size_t)N_DIM * K_DIM / 4)

__global__ __launch_bounds__(256)
void oal_wsplit_kernel(const float4* __restrict__ w4) {
    const size_t i = (size_t)blockIdx.x * blockDim.x + threadIdx.x;
    if (i >= NW4) return;
    float4 v = w4[i];
    __half2* hi = (__half2*)g_Whi;
    __half2* lo = (__half2*)g_Wlo;
    const size_t o = i * 2;

    __half2 h0 = __floats2half2_rn(v.x, v.y);
    __half2 h1 = __floats2half2_rn(v.z, v.w);
    float2 f0 = __half22float2(h0);
    float2 f1 = __half22float2(h1);
    hi[o]     = h0;
    hi[o + 1] = h1;
    lo[o]     = __floats2half2_rn(v.x - f0.x, v.y - f0.y);
    lo[o + 1] = __floats2half2_rn(v.z - f1.x, v.w - f1.y);
}

// ---------------------------------------------------------------------------
// GEMM: CTA 128x256, 8 warps (4M x 2N), warp tile 32x128, fp16 hi/lo 3-term.
// B via cp.async from pre-split g_W*; A split in-kernel from fp32.
// ---------------------------------------------------------------------------
__global__ __launch_bounds__(256, 1)
void oal_gemm_f16(const float* __restrict__ A,     // [M,K] fp32
                  const float* __restrict__ bias,
                  float* __restrict__ Y) {
    extern __shared__ char smem[];
    const uint32_t sb = smem_u32(smem);

    const int tid = threadIdx.x;
    const int lane = tid & 31;
    const int wid = tid >> 5;
    const int warp_m = (wid & 3) * 32;
    const int warp_n = (wid >> 2) * 128;
    const int block_m = blockIdx.y * BM;
    const int block_n = blockIdx.x * BN;

    // ldmatrix lane offsets (unswizzled; swizzle via XOR at use)
    const uint32_t swmask = (lane & 7) << 4;
    uint32_t a_off[2];
#pragma unroll
    for (int mt = 0; mt < 2; mt++) {
        uint32_t row = warp_m + mt * 16 + (lane & 15);
        a_off[mt] = row * 128 + (lane >> 4) * 16;
    }
    uint32_t b_off[8];
#pragma unroll
    for (int ntp = 0; ntp < 8; ntp++) {
        uint32_t n = warp_n + ntp * 16 + ((lane >> 4) & 1) * 8 + (lane & 7);
        b_off[ntp] = n * 128 + ((lane >> 3) & 1) * 16;
    }

    // producer mapping: thread owns rows {r8+32p}, 16B smem seg (tid&7)
    const int r8 = tid >> 3;
    const int c16 = (tid & 7) * 16;
    const int kseg8 = (tid & 7) * 8;

    const float*  Af  = A     + (size_t)(block_m + r8) * K_DIM + kseg8;
    const __half* Bhi = g_Whi + (size_t)(block_n + r8) * K_DIM + kseg8;
    const __half* Blo = g_Wlo + (size_t)(block_n + r8) * K_DIM + kseg8;

    float acc[2][16][4];
#pragma unroll
    for (int mt = 0; mt < 2; mt++)
#pragma unroll
        for (int nt = 0; nt < 16; nt++)
#pragma unroll
            for (int j = 0; j < 4; j++) acc[mt][nt][j] = 0.0f;

    float4 st[4][2];   // A staging: 8 fp32 per p-row

    auto a_load = [&](int c) {
        const int k0 = c * BK;
#pragma unroll
        for (int p = 0; p < 4; p++) {
            const float* src = Af + (size_t)(p * 32) * K_DIM + k0;
            st[p][0] = *(const float4*)(src);
            st[p][1] = *(const float4*)(src + 4);
        }
    };
    auto a_store = [&](int b) {   // split stage regs -> fp16 hi/lo into buffer b
        char* dst = smem + b * BUF_STRIDE;
#pragma unroll
        for (int p = 0; p < 4; p++) {
            const uint32_t sw = swz((r8 + p * 32) * 128 + c16);
            float4 u = st[p][0], v = st[p][1];
            __half2 h0 = __floats2half2_rn(u.x, u.y);
            __half2 h1 = __floats2half2_rn(u.z, u.w);
            __half2 h2 = __floats2half2_rn(v.x, v.y);
            __half2 h3 = __floats2half2_rn(v.z, v.w);
            float2 f0 = __half22float2(h0), f1 = __half22float2(h1);
            float2 f2 = __half22float2(h2), f3 = __half22float2(h3);
            __half2 l0 = __floats2half2_rn(u.x - f0.x, u.y - f0.y);
            __half2 l1 = __floats2half2_rn(u.z - f1.x, u.w - f1.y);
            __half2 l2 = __floats2half2_rn(v.x - f2.x, v.y - f2.y);
            __half2 l3 = __floats2half2_rn(v.z - f3.x, v.w - f3.y);
            uint4 hv = make_uint4(*(uint32_t*)&h0, *(uint32_t*)&h1,
                                  *(uint32_t*)&h2, *(uint32_t*)&h3);
            uint4 lv = make_uint4(*(uint32_t*)&l0, *(uint32_t*)&l1,
                                  *(uint32_t*)&l2, *(uint32_t*)&l3);
            *(uint4*)(dst + OFF_AHI + sw) = hv;
            *(uint4*)(dst + OFF_ALO + sw) = lv;
        }
    };
    auto b_fill = [&](int c, int b) {
        const uint32_t base = sb + b * BUF_STRIDE;
        const int k0 = c * BK;
#pragma unroll
        for (int p = 0; p < 8; p++) {
            const uint32_t sw = swz((r8 + p * 32) * 128 + c16);
            cp16(base + OFF_BHI + sw, Bhi + (size_t)(p * 32) * K_DIM + k0);
            cp16(base + OFF_BLO + sw, Blo + (size_t)(p * 32) * K_DIM + k0);
        }
    };

    // prologue: chunks 0 and 1; stage A chunk 2
    a_load(0); a_store(0);
    b_fill(0, 0); CP_COMMIT();
    a_load(1); a_store(1);
    b_fill(1, 1); CP_COMMIT();
    a_load(2);

    for (int c = 0; c < NCHUNKS; c++) {
        const int b = c & 1;
        const uint32_t cur = sb + b * BUF_STRIDE;

        CP_WAIT1();           // B group for buffer b complete
        __syncthreads();      // + all warps' A STS for buffer b visible

#pragma unroll
        for (int ks = 0; ks < 4; ks++) {
            uint32_t ah[2][4], al[2][4];
#pragma unroll
            for (int mt = 0; mt < 2; mt++) {
                const uint32_t ao = (a_off[mt] + ks * 32) ^ swmask;
                ldsm_x4(ah[mt], cur + OFF_AHI + ao);
                ldsm_x4(al[mt], cur + OFF_ALO + ao);
            }
#pragma unroll
            for (int ntp = 0; ntp < 8; ntp++) {
                const uint32_t bo = (b_off[ntp] + ks * 32) ^ swmask;
                uint32_t bh[4], bl[4];
                ldsm_x4(bh, cur + OFF_BHI + bo);
                ldsm_x4(bl, cur + OFF_BLO + bo);
                // term-major issue (R13): same acc quad every 4th HMMA;
                // per-quad order per k-step stays hh, hl, lh -> bit-identical
#pragma unroll
                for (int t = 0; t < 2; t++)
#pragma unroll
                    for (int mt = 0; mt < 2; mt++)
                        mma_f16(acc[mt][2 * ntp + t], ah[mt], bh + 2 * t);  // hi*hi
#pragma unroll
                for (int t = 0; t < 2; t++)
#pragma unroll
                    for (int mt = 0; mt < 2; mt++)
                        mma_f16(acc[mt][2 * ntp + t], ah[mt], bl + 2 * t);  // hi*lo
#pragma unroll
                for (int t = 0; t < 2; t++)
#pragma unroll
                    for (int mt = 0; mt < 2; mt++)
                        mma_f16(acc[mt][2 * ntp + t], al[mt], bh + 2 * t);  // lo*hi
            }
        }

        __syncthreads();      // all warps done reading buffer b
        if (c + 2 < NCHUNKS) {
            a_store(b);       // stage regs hold chunk c+2
            b_fill(c + 2, b);
        }
        CP_COMMIT();          // keep cp.async group counts aligned
        if (c + 3 < NCHUNKS) a_load(c + 3);   // LDG latency hides under next chunk
    }

    // ---- epilogue: acc -> gmem with bias ----
    const int g = lane >> 2;
    const int t4 = lane & 3;
#pragma unroll
    for (int mt = 0; mt < 2; mt++) {
        const int m0 = block_m + warp_m + mt * 16 + g;
#pragma unroll
        for (int nt = 0; nt < 16; nt++) {
            const int n0 = block_n + warp_n + nt * 8 + t4 * 2;
            const float2 bb = *(const float2*)(bias + n0);
            float2 v0, v1;
            v0.x = acc[mt][nt][0] + bb.x;
            v0.y = acc[mt][nt][1] + bb.y;
            v1.x = acc[mt][nt][2] + bb.x;
            v1.y = acc[mt][nt][3] + bb.y;
            *(float2*)(Y + (size_t)m0 * N_DIM + n0) = v0;
            *(float2*)(Y + (size_t)(m0 + 8) * N_DIM + n0) = v1;
        }
    }
}

// ---------------------------------------------------------------------------
// Per-token outlier-aware fake quant (66% of HBM peak).
// ---------------------------------------------------------------------------
#define QMAX 127.0f
#define OUTLIER_T 3.0f
#define Q_EPS 1e-6f

__global__ __launch_bounds__(256)
void oal_quant_kernel(float* __restrict__ Y) {
    const size_t row = blockIdx.x;
    float4* y4 = reinterpret_cast<float4*>(Y + row * (size_t)N_DIM);

    const int tid = threadIdx.x;
    float4 p = y4[tid];
    float4 q = y4[tid + 256];
    float v[8] = {p.x, p.y, p.z, p.w, q.x, q.y, q.z, q.w};

    float s = 0.0f, ss = 0.0f, amax = 0.0f;
#pragma unroll
    for (int i = 0; i < 8; i++) {
        s += v[i];
        ss = fmaf(v[i], v[i], ss);
        amax = fmaxf(amax, fabsf(v[i]));
    }
#pragma unroll
    for (int off = 16; off > 0; off >>= 1) {
        s += __shfl_xor_sync(0xFFFFFFFFu, s, off);
        ss += __shfl_xor_sync(0xFFFFFFFFu, ss, off);
        amax = fmaxf(amax, __shfl_xor_sync(0xFFFFFFFFu, amax, off));
    }

    __shared__ float red_s[8], red_ss[8], red_m[8];
    const int wid = tid >> 5;
    const int lid = tid & 31;
    if (lid == 0) { red_s[wid] = s; red_ss[wid] = ss; red_m[wid] = amax; }
    __syncthreads();

    if (wid == 0) {
        float s2 = (lid < 8) ? red_s[lid] : 0.0f;
        float ss2 = (lid < 8) ? red_ss[lid] : 0.0f;
        float m2 = (lid < 8) ? red_m[lid] : 0.0f;
#pragma unroll
        for (int off = 4; off > 0; off >>= 1) {
            s2 += __shfl_xor_sync(0xFFFFFFFFu, s2, off);
            ss2 += __shfl_xor_sync(0xFFFFFFFFu, ss2, off);
            m2 = fmaxf(m2, __shfl_xor_sync(0xFFFFFFFFu, m2, off));
        }
        if (lid == 0) { red_s[0] = s2; red_ss[0] = ss2; red_m[0] = m2; }
    }
    __syncthreads();

    const float inv_d = 1.0f / (float)N_DIM;
    const float mean = red_s[0] * inv_d;
    const float var = fmaxf(red_ss[0] * inv_d - mean * mean, 0.0f);
    const float thr = OUTLIER_T * sqrtf(var);
    const float scale = fmaxf(fminf(red_m[0], thr) / QMAX, Q_EPS);
    const float inv_scale = 1.0f / scale;

#pragma unroll
    for (int i = 0; i < 8; i++) {
        float x = v[i];
        float cl = fminf(fmaxf(x, -thr), thr);
        float fq = rintf(cl * inv_scale) * scale;
        v[i] = (fabsf(x) > thr) ? x : fq;
    }

    p.x = v[0]; p.y = v[1]; p.z = v[2]; p.w = v[3];
    q.x = v[4]; q.y = v[5]; q.z = v[6]; q.w = v[7];
    y4[tid] = p;
    y4[tid + 256] = q;
}

// ---------------------------------------------------------------------------

extern "C" void kernel_launch(void* const* d_in, const int* in_sizes, int n_in,
                              void* d_out, int out_size) {
    const float* x = (const float*)d_in[0];
    const float* W = (const float*)d_in[1];
    const float* b = (const float*)d_in[2];
    float* out = (float*)d_out;

    cudaFuncSetAttribute(oal_gemm_f16, cudaFuncAttributeMaxDynamicSharedMemorySize, SMEM_TOTAL);

    // 1) split W into fp16 hi/lo (16 MB, ~6us)
    const int sblocks = (int)((NW4 + 255) / 256);
    oal_wsplit_kernel<<<sblocks, 256>>>((const float4*)W);

    // 2) GEMM
    dim3 ggrid(N_DIM / BN, M_DIM / BM);   // (8, 128)
    oal_gemm_f16<<<ggrid, 256, SMEM_TOTAL>>>(x, b, out);

    // 3) per-token quant
    oal_quant_kernel<<<M_DIM, 256>>>(out);
}